// round 16
// baseline (speedup 1.0000x reference)
#include <cuda_runtime.h>
#include <cuda_bf16.h>
#include <math.h>

// Problem constants
#define B_   16
#define C_   256
#define S_   1024
#define NH_  8
#define DH_  32
#define NP_  8          // pairs
#define NPD_ 16         // pair-directions
#define M_   (B_ * S_)  // 16384 rows for batched GEMMs
#define SHARED_ELEMS (B_ * C_ * S_)   // 4194304

// GEMM smem geometry (words = bf16 pairs)
#define TSTRIDE    36
#define TILE_WORDS (128 * TSTRIDE)
#define GEMM_SMEM  (2 * 2 * TILE_WORDS * 4)   // 2 stages x (As+Ws) = 73728 B

// ---------------- scratch (device globals; no allocations) ----------------
__device__ float g_tokens[B_ * S_ * C_];   // (b,s,c) fp32
__device__ float g_qkv   [B_ * S_ * 3 * C_];
__device__ float g_new   [B_ * S_ * C_];   // updated tokens (b,s,c)
__device__ float g_misum [B_ * C_];
__device__ float g_gres  [NP_];            // res_scale * gate
// bf16 buffers (16B-aligned for vectorized access)
__device__ __align__(16) __nv_bfloat16 g_qb  [B_ * S_ * C_];   // LN(tokens)  (GEMM A, mode 0)
__device__ __align__(16) __nv_bfloat16 g_ctxb[NPD_ * S_ * C_]; // attention ctx (GEMM A, mode 1)
__device__ __align__(16) __nv_bfloat16 g_h1b [M_ * 1024];      // MLP hidden  (GEMM A, mode 3)
__device__ __align__(16) __nv_bfloat16 g_mln [M_ * C_];        // MLP-LN      (GEMM A, mode 2)
__device__ __align__(16) __nv_bfloat16 g_wqkv[768 * 256];
__device__ __align__(16) __nv_bfloat16 g_wout[256 * 256];
__device__ __align__(16) __nv_bfloat16 g_w1  [1024 * 256];
__device__ __align__(16) __nv_bfloat16 g_w2  [256 * 1024];

// ---------------------------------------------------------------------------
__global__ void zero_misum_kernel() {
    int i = blockIdx.x * 256 + threadIdx.x;
    if (i < B_ * C_) g_misum[i] = 0.f;
}

// Convert ALL weight matrices f32 -> bf16 in one kernel.
// Destination globals referenced in DEVICE code (true device addresses) —
// passing __device__ symbols as host-side kernel args silently writes to the
// host shadow on GB300 (ATS-coherent); that was the R8-R14 bug.
__global__ void cvt_weights_kernel(const float* __restrict__ wqkv_s,
                                   const float* __restrict__ wout_s,
                                   const float* __restrict__ w1_s,
                                   const float* __restrict__ w2_s) {
    int i = (blockIdx.x * 256 + threadIdx.x) * 4;
    const float* src;
    __nv_bfloat16* dst;
    int off;
    if (i < 196608)      { src = wqkv_s; dst = g_wqkv; off = i; }
    else if (i < 262144) { src = wout_s; dst = g_wout; off = i - 196608; }
    else if (i < 524288) { src = w1_s;   dst = g_w1;   off = i - 262144; }
    else                 { src = w2_s;   dst = g_w2;   off = i - 524288; }
    float4 v = *(const float4*)(src + off);
    *(__nv_bfloat162*)(dst + off)     = __floats2bfloat162_rn(v.x, v.y);
    *(__nv_bfloat162*)(dst + off + 2) = __floats2bfloat162_rn(v.z, v.w);
}

// Fused: transpose z_sem(b,c,s) -> tokens(b,s,c), LayerNorm -> g_qb (bf16), mean sums.
__global__ __launch_bounds__(256) void ln_tokens_kernel(const float* __restrict__ z,
                                 const float* __restrict__ ln_w,
                                 const float* __restrict__ ln_b) {
    int b  = blockIdx.y;
    int s0 = blockIdx.x * 32;
    __shared__ float tile[C_][33];
    __shared__ float sm[32], sr[32];
    int tid = threadIdx.x;
    const float* zb = z + (size_t)b * C_ * S_;
    #pragma unroll
    for (int it = 0; it < 32; ++it) {
        int e = it * 256 + tid;
        int c = e >> 5, sl = e & 31;
        tile[c][sl] = zb[c * S_ + s0 + sl];
    }
    __syncthreads();
    int t = tid >> 3, g = tid & 7;
    float sum = 0.f, sq = 0.f;
    #pragma unroll
    for (int k = 0; k < 32; ++k) {
        float v = tile[g + k * 8][t];
        sum += v; sq += v * v;
    }
    #pragma unroll
    for (int o = 1; o < 8; o <<= 1) {
        sum += __shfl_xor_sync(0xffffffffu, sum, o);
        sq  += __shfl_xor_sync(0xffffffffu, sq,  o);
    }
    if (g == 0) {
        float m = sum * (1.f / C_);
        sm[t] = m;
        sr[t] = rsqrtf(sq * (1.f / C_) - m * m + 1e-5f);
    }
    __syncthreads();
    float w  = ln_w[tid];
    float bb = ln_b[tid];
    float part = 0.f;
    #pragma unroll
    for (int sl = 0; sl < 32; ++sl) {
        float v  = tile[tid][sl];
        float qv = (v - sm[sl]) * sr[sl] * w + bb;
        size_t o = ((size_t)(b * S_ + s0 + sl)) * C_ + tid;
        g_tokens[o] = v;
        g_qb[o]     = __float2bfloat16(qv);
        part += qv;
    }
    atomicAdd(&g_misum[b * C_ + tid], part);
}

// Per-pair cosine similarity -> gate, sim; writes gate/sim to output tail.
__global__ void pair_stats_kernel(const int* __restrict__ pairs,
                                  const float* __restrict__ res_scale,
                                  const float* __restrict__ gate_scale,
                                  float* __restrict__ out_tail) {
    int p   = blockIdx.x;
    int tid = threadIdx.x;
    int bi  = pairs[2 * p], bj = pairs[2 * p + 1];
    float mi = g_misum[bi * C_ + tid] * (1.f / S_);
    float mj = g_misum[bj * C_ + tid] * (1.f / S_);
    float vals[3] = { mi * mj, mi * mi, mj * mj };
    __shared__ float sbuf[8];
    __shared__ float sres[3];
    int lane = tid & 31, wid = tid >> 5;
    for (int t = 0; t < 3; ++t) {
        float v = vals[t];
        #pragma unroll
        for (int o = 16; o; o >>= 1) v += __shfl_xor_sync(0xffffffffu, v, o);
        if (lane == 0) sbuf[wid] = v;
        __syncthreads();
        if (tid < 32) {
            float x = (tid < 8) ? sbuf[tid] : 0.f;
            #pragma unroll
            for (int o = 4; o; o >>= 1) x += __shfl_xor_sync(0xffffffffu, x, o);
            if (tid == 0) sres[t] = x;
        }
        __syncthreads();
    }
    if (tid == 0) {
        float ni = fmaxf(sqrtf(sres[1]), 1e-6f);
        float nj = fmaxf(sqrtf(sres[2]), 1e-6f);
        float sim  = sres[0] / (ni * nj);
        float gate = 1.f / (1.f + expf(-gate_scale[0] * sim));
        out_tail[p]       = gate;
        out_tail[8 + p]   = sim;
        g_gres[p] = res_scale[0] * gate;
    }
}

// ---------------- tensor-core helpers ----------------
__device__ __forceinline__ unsigned f2tf(float f) {
    unsigned u;
    asm("cvt.rna.tf32.f32 %0, %1;" : "=r"(u) : "f"(f));
    return u;
}
__device__ __forceinline__ void mma_tf32(float* d, const unsigned* a, const unsigned* b) {
    asm volatile(
        "mma.sync.aligned.m16n8k8.row.col.f32.tf32.tf32.f32 "
        "{%0,%1,%2,%3}, {%4,%5,%6,%7}, {%8,%9}, {%0,%1,%2,%3};\n"
        : "+f"(d[0]), "+f"(d[1]), "+f"(d[2]), "+f"(d[3])
        : "r"(a[0]), "r"(a[1]), "r"(a[2]), "r"(a[3]), "r"(b[0]), "r"(b[1]));
}
__device__ __forceinline__ void mma_bf16(float* d, const unsigned* a, const unsigned* b) {
    asm volatile(
        "mma.sync.aligned.m16n8k16.row.col.f32.bf16.bf16.f32 "
        "{%0,%1,%2,%3}, {%4,%5,%6,%7}, {%8,%9}, {%0,%1,%2,%3};\n"
        : "+f"(d[0]), "+f"(d[1]), "+f"(d[2]), "+f"(d[3])
        : "r"(a[0]), "r"(a[1]), "r"(a[2]), "r"(a[3]), "r"(b[0]), "r"(b[1]));
}
__device__ __forceinline__ void cp16(unsigned* dst_smem, const void* src_gmem) {
    unsigned d = (unsigned)__cvta_generic_to_shared(dst_smem);
    asm volatile("cp.async.cg.shared.global [%0], [%1], 16;\n" :: "r"(d), "l"(src_gmem));
}
__device__ __forceinline__ void cp_commit() {
    asm volatile("cp.async.commit_group;\n" ::: "memory");
}
__device__ __forceinline__ void cp_wait1() {
    asm volatile("cp.async.wait_group 1;\n" ::: "memory");
}

// ---------------- bf16 tensor-core GEMM, cp.async double-buffered ----------------
// mode 0: g_qb  @ g_wqkv -> g_qkv (fp32)                 (N=768,  K=256)
// mode 1: g_ctxb@ g_wout -> g_new = tokens + g*cross     (N=256,  K=256)
// mode 2: g_mln @ g_w1   -> g_h1b = gelu(.) (bf16)       (N=1024, K=256)
// mode 3: g_h1b @ g_w2   -> g_new += .                   (N=256,  K=1024)
// Block tile 128x128, BK=64 bf16 (32 words), 8 warps (2 m x 4 n), warp tile 64x32.
// Dynamic smem: 2 stages x (As + Ws), 128x36 words each.
__global__ __launch_bounds__(256) void gemm_bf_kernel(int mode,
                            const float* __restrict__ bias,
                            const int* __restrict__ pairs,
                            int K, int N) {
    const __nv_bfloat16* A;
    const __nv_bfloat16* W;
    if (mode == 0)      { A = g_qb;   W = g_wqkv; }
    else if (mode == 1) { A = g_ctxb; W = g_wout; }
    else if (mode == 2) { A = g_mln;  W = g_w1;   }
    else                { A = g_h1b;  W = g_w2;   }

    extern __shared__ unsigned sh[];   // [stage][As|Ws][128][36]

    int tid  = threadIdx.x;
    int lane = tid & 31, w = tid >> 5;
    int g  = lane >> 2, tg = lane & 3;
    int wm0 = (w >> 2) * 64;
    int wn0 = (w & 3) * 32;
    int rowM = blockIdx.y * 128;
    int colN = blockIdx.x * 128;

    float d[4][4][4];
    #pragma unroll
    for (int mi = 0; mi < 4; ++mi)
        #pragma unroll
        for (int ni = 0; ni < 4; ++ni)
            #pragma unroll
            for (int q = 0; q < 4; ++q) d[mi][ni][q] = 0.f;

    const __nv_bfloat16* Abase = A + (size_t)rowM * K;
    const __nv_bfloat16* Wbase = W + (size_t)colN * K;

    // stage pointers
    auto stage_As = [&](int st) { return sh + st * (2 * TILE_WORDS); };
    auto stage_Ws = [&](int st) { return sh + st * (2 * TILE_WORDS) + TILE_WORDS; };

    // issue async copies for one K-tile into a stage
    auto stage_load = [&](int st, int k0) {
        unsigned* As = stage_As(st);
        unsigned* Ws = stage_Ws(st);
        #pragma unroll
        for (int i = 0; i < 4; ++i) {
            int f  = tid + i * 256;            // 0..1023
            int r  = f >> 3;
            int c4 = (f & 7) * 4;              // word offset 0..28
            cp16(&As[r * TSTRIDE + c4], Abase + (size_t)r * K + k0 + c4 * 2);
            cp16(&Ws[r * TSTRIDE + c4], Wbase + (size_t)r * K + k0 + c4 * 2);
        }
    };

    int nk = K >> 6;                           // K / 64
    stage_load(0, 0);
    cp_commit();

    for (int it = 0; it < nk; ++it) {
        int cur = it & 1;
        if (it + 1 < nk) stage_load((it + 1) & 1, (it + 1) * 64);
        cp_commit();                           // (empty group on last iter keeps accounting)
        cp_wait1();                            // current stage's data has landed
        __syncthreads();

        const unsigned* As = stage_As(cur);
        const unsigned* Ws = stage_Ws(cur);
        #pragma unroll
        for (int ks = 0; ks < 32; ks += 8) {   // ks in words (16 bf16 = 8 words)
            unsigned a[4][4], b[4][2];
            #pragma unroll
            for (int mi = 0; mi < 4; ++mi) {
                int r = wm0 + mi * 16 + g;
                a[mi][0] = As[r * TSTRIDE + ks + tg];
                a[mi][1] = As[(r + 8) * TSTRIDE + ks + tg];
                a[mi][2] = As[r * TSTRIDE + ks + tg + 4];
                a[mi][3] = As[(r + 8) * TSTRIDE + ks + tg + 4];
            }
            #pragma unroll
            for (int ni = 0; ni < 4; ++ni) {
                int n = wn0 + ni * 8 + g;
                b[ni][0] = Ws[n * TSTRIDE + ks + tg];
                b[ni][1] = Ws[n * TSTRIDE + ks + tg + 4];
            }
            #pragma unroll
            for (int mi = 0; mi < 4; ++mi)
                #pragma unroll
                for (int ni = 0; ni < 4; ++ni)
                    mma_bf16(d[mi][ni], a[mi], b[ni]);
        }
        __syncthreads();                       // protects stage overwritten next iter
    }

    float bc[4][2];
    int ccol[4];
    #pragma unroll
    for (int ni = 0; ni < 4; ++ni) {
        int c0 = colN + wn0 + ni * 8 + tg * 2;
        ccol[ni] = c0;
        bc[ni][0] = bias[c0];
        bc[ni][1] = bias[c0 + 1];
    }

    #pragma unroll
    for (int mi = 0; mi < 4; ++mi) {
        #pragma unroll
        for (int half = 0; half < 2; ++half) {
            int row = rowM + wm0 + mi * 16 + g + half * 8;
            int pd = row >> 10, s = row & 1023;
            int qb = 0; float gr = 0.f;
            if (mode == 1 || mode == 3) {
                qb = pairs[pd];
                gr = g_gres[pd >> 1];
            }
            #pragma unroll
            for (int ni = 0; ni < 4; ++ni) {
                float v0 = d[mi][ni][half * 2 + 0] + bc[ni][0];
                float v1 = d[mi][ni][half * 2 + 1] + bc[ni][1];
                int c0 = ccol[ni];
                if (mode == 0) {
                    g_qkv[(size_t)row * 768 + c0]     = v0;
                    g_qkv[(size_t)row * 768 + c0 + 1] = v1;
                } else if (mode == 2) {
                    float h0 = 0.5f * v0 * (1.f + erff(v0 * 0.7071067811865476f));
                    float h1 = 0.5f * v1 * (1.f + erff(v1 * 0.7071067811865476f));
                    *(__nv_bfloat162*)&g_h1b[(size_t)row * 1024 + c0] = __floats2bfloat162_rn(h0, h1);
                } else {
                    size_t idx = ((size_t)(qb * S_ + s)) * C_ + c0;
                    if (mode == 1) {
                        // pairs is a permutation of 0..15 -> every row of g_new written here
                        g_new[idx]     = g_tokens[idx]     + gr * v0;
                        g_new[idx + 1] = g_tokens[idx + 1] + gr * v1;
                    } else {
                        g_new[idx]     += v0;
                        g_new[idx + 1] += v1;
                    }
                }
            }
        }
    }
}

// ---------------- tensor-core flash attention over (pd, head, 128-row q-tile) ---
// QK^T in tf32 mma; softmax via exp2 (scores tiny -> no max subtraction);
// P stored bf16 in per-warp smem region; P@V in bf16 mma with V^T bf16 in smem.
// ctx written bf16 to g_ctxb.
__global__ __launch_bounds__(256) void attn_tc_kernel(const int* __restrict__ pairs) {
    const int pd = blockIdx.z;
    const int h  = blockIdx.y;
    const int q0 = blockIdx.x * 128;
    const int qb = pairs[pd];
    const int kb = pairs[pd ^ 1];

    __shared__ float         Ks[64][36];   // K tile [key][d], fp32
    __shared__ __nv_bfloat16 Vt[32][72];   // V^T tile [d][key], bf16
    __shared__ __nv_bfloat16 Ps[128][72];  // P tile [row][key], bf16

    int tid = threadIdx.x, lane = tid & 31, w = tid >> 5;
    int g = lane >> 2, tg = lane & 3;
    int wm = w * 16;

    const float QS = 0.17677669529663687f * 1.4426950408889634f;
    unsigned qa[4][4];
    {
        const float* Qb = g_qkv + (size_t)(qb * S_ + q0 + wm) * 768 + h * 32;
        #pragma unroll
        for (int ks = 0; ks < 4; ++ks) {
            qa[ks][0] = f2tf(Qb[(size_t)g       * 768 + ks * 8 + tg    ] * QS);
            qa[ks][1] = f2tf(Qb[(size_t)(g + 8) * 768 + ks * 8 + tg    ] * QS);
            qa[ks][2] = f2tf(Qb[(size_t)g       * 768 + ks * 8 + tg + 4] * QS);
            qa[ks][3] = f2tf(Qb[(size_t)(g + 8) * 768 + ks * 8 + tg + 4] * QS);
        }
    }

    float O[4][4];
    #pragma unroll
    for (int ni = 0; ni < 4; ++ni)
        #pragma unroll
        for (int q = 0; q < 4; ++q) O[ni][q] = 0.f;
    float l0 = 0.f, l1 = 0.f;

    for (int kt = 0; kt < 16; ++kt) {
        int k0 = kt * 64;
        __syncthreads();
        #pragma unroll
        for (int i = 0; i < 2; ++i) {
            int f = tid + i * 256;
            int r = f >> 3, c4 = (f & 7) * 4;
            float4 v = *(const float4*)(g_qkv + (size_t)(kb * S_ + k0 + r) * 768 + 256 + h * 32 + c4);
            *(float4*)&Ks[r][c4] = v;
        }
        #pragma unroll
        for (int i = 0; i < 4; ++i) {
            int u = tid + i * 256;
            int r = u >> 4, dp = (u & 15) * 2;
            float2 v = *(const float2*)(g_qkv + (size_t)(kb * S_ + k0 + r) * 768 + 512 + h * 32 + dp);
            Vt[dp][r]     = __float2bfloat16(v.x);
            Vt[dp + 1][r] = __float2bfloat16(v.y);
        }
        __syncthreads();

        float sacc[8][4];
        #pragma unroll
        for (int ni = 0; ni < 8; ++ni)
            #pragma unroll
            for (int q = 0; q < 4; ++q) sacc[ni][q] = 0.f;
        #pragma unroll
        for (int ks = 0; ks < 4; ++ks) {
            #pragma unroll
            for (int ni = 0; ni < 8; ++ni) {
                unsigned b[2];
                b[0] = f2tf(Ks[ni * 8 + g][ks * 8 + tg]);
                b[1] = f2tf(Ks[ni * 8 + g][ks * 8 + tg + 4]);
                mma_tf32(sacc[ni], qa[ks], b);
            }
        }

        float rs0 = 0.f, rs1 = 0.f;
        #pragma unroll
        for (int ni = 0; ni < 8; ++ni) {
            float e0 = exp2f(sacc[ni][0]);
            float e1 = exp2f(sacc[ni][1]);
            float e2 = exp2f(sacc[ni][2]);
            float e3 = exp2f(sacc[ni][3]);
            rs0 += e0 + e1;
            rs1 += e2 + e3;
            *(__nv_bfloat162*)&Ps[wm + g    ][ni * 8 + tg * 2] = __floats2bfloat162_rn(e0, e1);
            *(__nv_bfloat162*)&Ps[wm + 8 + g][ni * 8 + tg * 2] = __floats2bfloat162_rn(e2, e3);
        }
        rs0 += __shfl_xor_sync(0xffffffffu, rs0, 1);
        rs0 += __shfl_xor_sync(0xffffffffu, rs0, 2);
        rs1 += __shfl_xor_sync(0xffffffffu, rs1, 1);
        rs1 += __shfl_xor_sync(0xffffffffu, rs1, 2);
        l0 += rs0;
        l1 += rs1;
        __syncwarp();

        #pragma unroll
        for (int ks = 0; ks < 4; ++ks) {
            unsigned a[4];
            a[0] = *(const unsigned*)&Ps[wm + g    ][ks * 16 + tg * 2];
            a[1] = *(const unsigned*)&Ps[wm + 8 + g][ks * 16 + tg * 2];
            a[2] = *(const unsigned*)&Ps[wm + g    ][ks * 16 + tg * 2 + 8];
            a[3] = *(const unsigned*)&Ps[wm + 8 + g][ks * 16 + tg * 2 + 8];
            #pragma unroll
            for (int ni = 0; ni < 4; ++ni) {
                unsigned b[2];
                b[0] = *(const unsigned*)&Vt[ni * 8 + g][ks * 16 + tg * 2];
                b[1] = *(const unsigned*)&Vt[ni * 8 + g][ks * 16 + tg * 2 + 8];
                mma_bf16(O[ni], a, b);
            }
        }
    }

    float inv0 = 1.f / l0, inv1 = 1.f / l1;
    #pragma unroll
    for (int ni = 0; ni < 4; ++ni) {
        size_t o0 = (size_t)(pd * S_ + q0 + wm + g    ) * C_ + h * 32 + ni * 8 + tg * 2;
        size_t o1 = (size_t)(pd * S_ + q0 + wm + 8 + g) * C_ + h * 32 + ni * 8 + tg * 2;
        *(__nv_bfloat162*)&g_ctxb[o0] = __floats2bfloat162_rn(O[ni][0] * inv0, O[ni][1] * inv0);
        *(__nv_bfloat162*)&g_ctxb[o1] = __floats2bfloat162_rn(O[ni][2] * inv1, O[ni][3] * inv1);
    }
}

// ---------------- MLP LayerNorm on updated tokens -> g_mln (bf16) ---------------
__global__ __launch_bounds__(256) void mlp_ln_kernel(const int* __restrict__ pairs,
                              const float* __restrict__ w,
                              const float* __restrict__ b) {
    int slot = blockIdx.y;
    int qb   = pairs[slot];
    int warp = threadIdx.x >> 5, lane = threadIdx.x & 31;
    int tok  = blockIdx.x * 8 + warp;
    const float* x = g_new + (size_t)(qb * S_ + tok) * C_;
    float v[8], sum = 0.f, sq = 0.f;
    #pragma unroll
    for (int t = 0; t < 8; ++t) {
        v[t] = x[lane + t * 32];
        sum += v[t]; sq += v[t] * v[t];
    }
    #pragma unroll
    for (int o = 16; o; o >>= 1) {
        sum += __shfl_xor_sync(0xffffffffu, sum, o);
        sq  += __shfl_xor_sync(0xffffffffu, sq,  o);
    }
    float mean = sum * (1.f / C_);
    float rinv = rsqrtf(sq * (1.f / C_) - mean * mean + 1e-5f);
    __nv_bfloat16* y = g_mln + (size_t)(slot * S_ + tok) * C_;
    #pragma unroll
    for (int t = 0; t < 8; ++t) {
        int c = lane + t * 32;
        y[c] = __float2bfloat16((v[t] - mean) * rinv * w[c] + b[c]);
    }
}

// ---------------- final transpose: g_new(b,s,c) -> out(b,c,h,w) -----------------
__global__ void out_transpose_kernel(float* __restrict__ out) {
    __shared__ float tile[32][33];
    int b  = blockIdx.z;
    int c0 = blockIdx.y * 32;
    int s0 = blockIdx.x * 32;
    int tx = threadIdx.x, ty = threadIdx.y;
    #pragma unroll
    for (int i = 0; i < 32; i += 8)
        tile[ty + i][tx] = g_new[(size_t)(b * S_ + s0 + ty + i) * C_ + c0 + tx];
    __syncthreads();
    #pragma unroll
    for (int i = 0; i < 32; i += 8)
        out[(size_t)b * C_ * S_ + (size_t)(c0 + ty + i) * S_ + s0 + tx] = tile[tx][ty + i];
}

// ---------------------------------------------------------------------------
extern "C" void kernel_launch(void* const* d_in, const int* in_sizes, int n_in,
                              void* d_out, int out_size) {
    const float* z          = (const float*)d_in[0];
    const int*   pairs      = (const int*)  d_in[1];
    const float* ln_w       = (const float*)d_in[2];
    const float* ln_b       = (const float*)d_in[3];
    const float* in_proj_w  = (const float*)d_in[4];
    const float* in_proj_b  = (const float*)d_in[5];
    const float* out_proj_w = (const float*)d_in[6];
    const float* out_proj_b = (const float*)d_in[7];
    const float* res_scale  = (const float*)d_in[8];
    const float* gate_scale = (const float*)d_in[9];
    const float* mlp_ln_w   = (const float*)d_in[10];
    const float* mlp_ln_b   = (const float*)d_in[11];
    const float* mlp_w1     = (const float*)d_in[12];
    const float* mlp_b1     = (const float*)d_in[13];
    const float* mlp_w2     = (const float*)d_in[14];
    const float* mlp_b2     = (const float*)d_in[15];
    float* out = (float*)d_out;

    // opt-in dynamic smem for the double-buffered GEMM (idempotent host call)
    cudaFuncSetAttribute(gemm_bf_kernel, cudaFuncAttributeMaxDynamicSharedMemorySize, GEMM_SMEM);

    zero_misum_kernel<<<16, 256>>>();
    cvt_weights_kernel<<<768, 256>>>(in_proj_w, out_proj_w, mlp_w1, mlp_w2);

    ln_tokens_kernel<<<dim3(32, 16), 256>>>(z, ln_w, ln_b);
    pair_stats_kernel<<<8, 256>>>(pairs, res_scale, gate_scale, out + SHARED_ELEMS);

    // QKV projection: (16384 x 256) @ (768 x 256)^T
    gemm_bf_kernel<<<dim3(6, 128), 256, GEMM_SMEM>>>(0, in_proj_b, pairs, 256, 768);

    // attention: 8 q-tiles x 8 heads x 16 pair-directions (tensor-core)
    attn_tc_kernel<<<dim3(8, 8, 16), 256>>>(pairs);

    // out projection + gated residual (pairs is a permutation -> writes all of g_new)
    gemm_bf_kernel<<<dim3(2, 128), 256, GEMM_SMEM>>>(1, out_proj_b, pairs, 256, 256);

    // MLP
    mlp_ln_kernel<<<dim3(128, 16), 256>>>(pairs, mlp_ln_w, mlp_ln_b);
    gemm_bf_kernel<<<dim3(8, 128), 256, GEMM_SMEM>>>(2, mlp_b1, pairs, 256, 1024);
    gemm_bf_kernel<<<dim3(2, 128), 256, GEMM_SMEM>>>(3, mlp_b2, pairs, 1024, 256);

    // writeback
    out_transpose_kernel<<<dim3(32, 8, 16), dim3(32, 8)>>>(out);
}